// round 4
// baseline (speedup 1.0000x reference)
#include <cuda_runtime.h>

#define NB   8
#define LIN  32768
#define NC1  51
#define NK1  79
#define NSC  9
#define LP1  8192

// scratch (allocation-free rule: device globals)
__device__ float  g_bufA[30081024];   // max 8*51*9*8192
__device__ float  g_bufB[7520256];    // max 8*51*9*2048
__device__ double g_sum[408];
__device__ double g_sqs[408];

// ---------------------------------------------------------------------------
__global__ void zero_stats_kernel() {
    int i = blockIdx.x * blockDim.x + threadIdx.x;
    if (i < 408) { g_sum[i] = 0.0; g_sqs[i] = 0.0; }
}

// ---------------------------------------------------------------------------
// Lift (K=79, dilation 2^s, /2^s) fused with pool4.
// Block: 416 thr (13 warps). warp w = channel group (4 co), lane = pooled pos.
// Thread tile: 4 co x 4 raw l -> 16 FFMA per k-step.
// ---------------------------------------------------------------------------
__launch_bounds__(416)
__global__ void lift_pool_kernel(const float* __restrict__ x,
                                 const float* __restrict__ w,
                                 float* __restrict__ out, int s)
{
    extern __shared__ float sm[];
    float* sw = sm;             // [79][52] pre-scaled weights
    float* sx = sm + 79 * 52;   // input window
    const int d = 1 << s;
    const float invd = 1.0f / (float)d;
    const int b   = blockIdx.y;
    const int l0  = blockIdx.x * 128;
    const int tid = threadIdx.x;

    for (int t = tid; t < 79 * 52; t += 416) {
        int k = t / 52, co = t - k * 52;
        sw[t] = (co < NC1) ? w[co * NK1 + k] * invd : 0.0f;
    }
    const int nx = 128 + 78 * d + 8;
    const int gb = l0 - 39 * d;
    const float* xb = x + (size_t)b * LIN;
    for (int t = tid; t < nx; t += 416) {
        int g = gb + t;
        sx[t] = (g >= 0 && g < LIN) ? xb[g] : 0.0f;
    }
    __syncthreads();

    const int lg   = tid & 31;
    const int cg   = tid >> 5;
    const int co0  = cg * 4;
    const int base = lg * 4;
    float acc[4][4] = {};

    if (d >= 4) {
        #pragma unroll 4
        for (int k = 0; k < NK1; ++k) {
            float4 xv = *reinterpret_cast<const float4*>(&sx[base + k * d]);
            float4 wv = *reinterpret_cast<const float4*>(&sw[k * 52 + co0]);
            float xa[4] = {xv.x, xv.y, xv.z, xv.w};
            float wa[4] = {wv.x, wv.y, wv.z, wv.w};
            #pragma unroll
            for (int r = 0; r < 4; ++r)
                #pragma unroll
                for (int j = 0; j < 4; ++j)
                    acc[r][j] = fmaf(wa[r], xa[j], acc[r][j]);
        }
    } else if (d == 2) {
        float x0 = sx[base], x1 = sx[base+1], x2 = sx[base+2], x3 = sx[base+3];
        for (int k = 0; k < NK1; ++k) {
            float4 wv = *reinterpret_cast<const float4*>(&sw[k * 52 + co0]);
            float wa[4] = {wv.x, wv.y, wv.z, wv.w};
            float xa[4] = {x0, x1, x2, x3};
            #pragma unroll
            for (int r = 0; r < 4; ++r)
                #pragma unroll
                for (int j = 0; j < 4; ++j)
                    acc[r][j] = fmaf(wa[r], xa[j], acc[r][j]);
            x0 = x2; x1 = x3;
            x2 = sx[base + 2*k + 4];
            x3 = sx[base + 2*k + 5];
        }
    } else {
        float x0 = sx[base], x1 = sx[base+1], x2 = sx[base+2], x3 = sx[base+3];
        for (int k = 0; k < NK1; ++k) {
            float4 wv = *reinterpret_cast<const float4*>(&sw[k * 52 + co0]);
            float wa[4] = {wv.x, wv.y, wv.z, wv.w};
            float xa[4] = {x0, x1, x2, x3};
            #pragma unroll
            for (int r = 0; r < 4; ++r)
                #pragma unroll
                for (int j = 0; j < 4; ++j)
                    acc[r][j] = fmaf(wa[r], xa[j], acc[r][j]);
            x0 = x1; x1 = x2; x2 = x3;
            x3 = sx[base + k + 4];
        }
    }

    const int lp = blockIdx.x * 32 + lg;
    #pragma unroll
    for (int r = 0; r < 4; ++r) {
        int co = co0 + r;
        if (co < NC1) {
            float m = fmaxf(fmaxf(acc[r][0], acc[r][1]), fmaxf(acc[r][2], acc[r][3]));
            out[(((size_t)b * NC1 + co) * NSC + s) * LP1 + lp] = m;
        }
    }
}

// ---------------------------------------------------------------------------
// GConvGG: tiled GEMM over ci per (i,k). Block tile COT x LT, thread tile 4x4.
// out[b,co,s,l] = sum_{i,ci,k} in[b,ci,s+i,l+(k-1)*2^(s+i)] * w[co,ci,i,k]/2^(s+i)
// ---------------------------------------------------------------------------
template <int COT, int LT>
__launch_bounds__((COT/4)*(LT/4))
__global__ void gg_kernel(const float* __restrict__ in, const float* __restrict__ w,
                          float* __restrict__ out,
                          int Cin, int Cout, int Hin, int Nk, int L)
{
    const int CIC = 16;
    const int TLn = LT / 4;
    const int NT  = (COT/4) * TLn;
    __shared__ float As[CIC][COT];
    __shared__ float Bs[CIC][LT];

    const int Hout = Hin - Nk + 1;
    const int s   = blockIdx.z % Hout;
    const int b   = blockIdx.z / Hout;
    const int co0 = blockIdx.y * COT;
    const int l0  = blockIdx.x * LT;
    const int tid = threadIdx.x;
    const int tco = (tid / TLn) * 4;
    const int tl  = (tid % TLn) * 4;

    float acc[4][4] = {};

    for (int i = 0; i < Nk; ++i) {
        const int d = 1 << (s + i);
        const float invd = 1.0f / (float)d;
        const float* inb = in + (((size_t)b * Cin) * Hin + (s + i)) * L;
        for (int k = 0; k < 3; ++k) {
            const int off = (k - 1) * d;
            for (int cc = 0; cc < Cin; cc += CIC) {
                __syncthreads();
                for (int t = tid; t < CIC * COT; t += NT) {
                    int ci = cc + t / COT, co = co0 + (t % COT);
                    float v = 0.0f;
                    if (ci < Cin && co < Cout)
                        v = w[(((size_t)co * Cin + ci) * Nk + i) * 3 + k] * invd;
                    As[t / COT][t % COT] = v;
                }
                for (int t = tid; t < CIC * LT; t += NT) {
                    int ci = cc + t / LT;
                    int l  = l0 + off + (t % LT);
                    float v = 0.0f;
                    if (ci < Cin && l >= 0 && l < L)
                        v = inb[(size_t)ci * Hin * L + l];
                    Bs[t / LT][t % LT] = v;
                }
                __syncthreads();
                #pragma unroll
                for (int ci = 0; ci < CIC; ++ci) {
                    float4 av = *reinterpret_cast<const float4*>(&As[ci][tco]);
                    float4 bv = *reinterpret_cast<const float4*>(&Bs[ci][tl]);
                    float a4[4] = {av.x, av.y, av.z, av.w};
                    float b4[4] = {bv.x, bv.y, bv.z, bv.w};
                    #pragma unroll
                    for (int r = 0; r < 4; ++r)
                        #pragma unroll
                        for (int c = 0; c < 4; ++c)
                            acc[r][c] = fmaf(a4[r], b4[c], acc[r][c]);
                }
            }
        }
    }

    #pragma unroll
    for (int r = 0; r < 4; ++r) {
        int co = co0 + tco + r;
        if (co < Cout) {
            size_t ob = (((size_t)b * Cout + co) * Hout + s) * L + l0 + tl;
            #pragma unroll
            for (int c = 0; c < 4; ++c) out[ob + c] = acc[r][c];
        }
    }
}

// ---------------------------------------------------------------------------
// BN stats: per-channel sum/sumsq over (B,H,L). fp32 partials, double atomics.
// grid = (C, splits), block = 256
// ---------------------------------------------------------------------------
__global__ void stats_kernel(const float* __restrict__ in, int C, int HL)
{
    const int c  = blockIdx.x;
    const int sp = blockIdx.y, S = gridDim.y;
    float s = 0.0f, s2 = 0.0f;
    for (int b = 0; b < NB; ++b) {
        const float* p = in + ((size_t)b * C + c) * HL;
        for (int r = sp * blockDim.x + threadIdx.x; r < HL; r += S * blockDim.x) {
            float v = p[r];
            s += v; s2 = fmaf(v, v, s2);
        }
    }
    __shared__ float rs[256], rq[256];
    rs[threadIdx.x] = s; rq[threadIdx.x] = s2;
    __syncthreads();
    for (int st = 128; st > 0; st >>= 1) {
        if (threadIdx.x < st) {
            rs[threadIdx.x] += rs[threadIdx.x + st];
            rq[threadIdx.x] += rq[threadIdx.x + st];
        }
        __syncthreads();
    }
    if (threadIdx.x == 0) {
        atomicAdd(&g_sum[c], (double)rs[0]);
        atomicAdd(&g_sqs[c], (double)rq[0]);
    }
}

// ---------------------------------------------------------------------------
// BN apply + ReLU (+ optional fused pool4).
// ---------------------------------------------------------------------------
template <bool POOL>
__global__ void bn_relu_kernel(const float* __restrict__ in, float* __restrict__ out,
                               const float* __restrict__ gamma, const float* __restrict__ beta,
                               double invN, int C, int H, int Lin)
{
    __shared__ float ssc[408], ssh[408];
    for (int c = threadIdx.x; c < C; c += blockDim.x) {
        double m   = g_sum[c] * invN;
        double var = g_sqs[c] * invN - m * m;
        float inv = rsqrtf((float)var + 2e-5f);
        float sc  = gamma[c] * inv;
        ssc[c] = sc;
        ssh[c] = beta[c] - (float)m * sc;
    }
    __syncthreads();

    const int Lout = POOL ? (Lin / 4) : Lin;
    const size_t n = (size_t)NB * C * H * Lout;
    for (size_t i = (size_t)blockIdx.x * blockDim.x + threadIdx.x; i < n;
         i += (size_t)gridDim.x * blockDim.x) {
        int lp = (int)(i % Lout);
        size_t t = i / Lout;
        int h = (int)(t % H); t /= H;           // t = b*C + c
        int c = (int)(t % C);
        size_t ibase = (t * (size_t)H + h) * (size_t)Lin;
        float sc = ssc[c], sh = ssh[c];
        float y;
        if (POOL) {
            const float* p = in + ibase + 4 * (size_t)lp;
            float y0 = fmaf(p[0], sc, sh);
            float y1 = fmaf(p[1], sc, sh);
            float y2 = fmaf(p[2], sc, sh);
            float y3 = fmaf(p[3], sc, sh);
            y = fmaxf(fmaxf(y0, y1), fmaxf(y2, y3));
        } else {
            y = fmaf(in[ibase + lp], sc, sh);
        }
        out[i] = fmaxf(y, 0.0f);
    }
}

// ---------------------------------------------------------------------------
// Final: mean over L=32, 1x1 classifier w11 [10,408] -> out [8,10]
// ---------------------------------------------------------------------------
__global__ void final_kernel(const float* __restrict__ in,   // [8][408][32]
                             const float* __restrict__ w11,
                             float* __restrict__ out)
{
    __shared__ float mean[NB * 408];
    for (int i = threadIdx.x; i < NB * 408; i += blockDim.x) {
        const float* p = in + (size_t)i * 32;
        float s = 0.0f;
        #pragma unroll
        for (int j = 0; j < 32; ++j) s += p[j];
        mean[i] = s * (1.0f / 32.0f);
    }
    __syncthreads();
    for (int i = threadIdx.x; i < NB * 10; i += blockDim.x) {
        int b = i / 10, cls = i - b * 10;
        const float* mb = &mean[b * 408];
        const float* wr = &w11[cls * 408];
        float s = 0.0f;
        for (int ci = 0; ci < 408; ++ci) s = fmaf(mb[ci], wr[ci], s);
        out[i] = s;
    }
}

// ---------------------------------------------------------------------------
// Host side
// ---------------------------------------------------------------------------
static void bn_stage(const float* in, float* out, const float* g, const float* bta,
                     int C, int H, int Lin, bool pool)
{
    int HL = H * Lin;
    zero_stats_kernel<<<2, 256>>>();
    int S = (NB * HL) / (256 * 16);
    if (S < 1) S = 1; if (S > 64) S = 64;
    stats_kernel<<<dim3(C, S), 256>>>(in, C, HL);
    int Lout = pool ? Lin / 4 : Lin;
    size_t n = (size_t)NB * C * H * Lout;
    int grid = (int)((n + 255) / 256);
    if (grid > 8192) grid = 8192;
    double invN = 1.0 / ((double)NB * HL);
    if (pool) bn_relu_kernel<true ><<<grid, 256>>>(in, out, g, bta, invN, C, H, Lin);
    else      bn_relu_kernel<false><<<grid, 256>>>(in, out, g, bta, invN, C, H, Lin);
}

static void gg(const float* in, const float* w, float* out,
               int Cin, int Cout, int Hin, int Nk, int L)
{
    int Hout = Hin - Nk + 1;
    if (L >= 64)
        gg_kernel<64, 64><<<dim3(L / 64, (Cout + 63) / 64, NB * Hout), 256>>>(
            in, w, out, Cin, Cout, Hin, Nk, L);
    else
        gg_kernel<64, 32><<<dim3(L / 32, (Cout + 63) / 64, NB * Hout), 128>>>(
            in, w, out, Cin, Cout, Hin, Nk, L);
}

extern "C" void kernel_launch(void* const* d_in, const int* in_sizes, int n_in,
                              void* d_out, int out_size)
{
    const float* x   = (const float*)d_in[0];
    const float* w1  = (const float*)d_in[1];
    const float* w2  = (const float*)d_in[2];
    const float* w3  = (const float*)d_in[3];
    const float* w4  = (const float*)d_in[4];
    const float* w5  = (const float*)d_in[5];
    const float* w6  = (const float*)d_in[6];
    const float* w7  = (const float*)d_in[7];
    const float* w8  = (const float*)d_in[8];
    const float* w9  = (const float*)d_in[9];
    const float* w10 = (const float*)d_in[10];
    const float* w11 = (const float*)d_in[11];
    const float* gb[20];
    for (int i = 0; i < 20; ++i) gb[i] = (const float*)d_in[12 + i];

    float *A, *B;
    cudaGetSymbolAddress((void**)&A, g_bufA);
    cudaGetSymbolAddress((void**)&B, g_bufB);

    cudaFuncSetAttribute(lift_pool_kernel,
                         cudaFuncAttributeMaxDynamicSharedMemorySize, 98304);

    // lift + pool4 -> A [8,51,9,8192]
    for (int s = 0; s < NSC; ++s) {
        int d = 1 << s;
        size_t smem = (size_t)(79 * 52 + 128 + 78 * d + 8) * sizeof(float);
        lift_pool_kernel<<<dim3(LIN / 128, NB), 416, smem>>>(x, w1, A, s);
    }

    bn_stage(A, B, gb[0], gb[1], 51, 9, 8192, true);   // -> B [8,51,9,2048]
    gg(B, w2, A, 51, 51, 9, 3, 2048);                  // -> A [8,51,7,2048]
    bn_stage(A, B, gb[2], gb[3], 51, 7, 2048, false);
    gg(B, w3, A, 51, 51, 7, 1, 2048);
    bn_stage(A, B, gb[4], gb[5], 51, 7, 2048, true);   // -> B [8,51,7,512]
    gg(B, w4, A, 51, 102, 7, 3, 512);                  // -> A [8,102,5,512]
    bn_stage(A, B, gb[6], gb[7], 102, 5, 512, false);
    gg(B, w5, A, 102, 102, 5, 1, 512);
    bn_stage(A, B, gb[8], gb[9], 102, 5, 512, true);   // -> B [8,102,5,128]
    gg(B, w6, A, 102, 204, 5, 3, 128);                 // -> A [8,204,3,128]
    bn_stage(A, B, gb[10], gb[11], 204, 3, 128, false);
    gg(B, w7, A, 204, 204, 3, 1, 128);
    bn_stage(A, B, gb[12], gb[13], 204, 3, 128, false);
    gg(B, w8, A, 204, 204, 3, 1, 128);
    bn_stage(A, B, gb[14], gb[15], 204, 3, 128, true); // -> B [8,204,3,32]
    gg(B, w9, A, 204, 408, 3, 3, 32);                  // -> A [8,408,1,32]
    bn_stage(A, B, gb[16], gb[17], 408, 1, 32, false);
    gg(B, w10, A, 408, 408, 1, 1, 32);
    bn_stage(A, B, gb[18], gb[19], 408, 1, 32, false); // -> B [8,408,1,32]

    final_kernel<<<1, 512>>>(B, w11, (float*)d_out);
}

// round 5
// speedup vs baseline: 1.1228x; 1.1228x over previous
#include <cuda_runtime.h>

#define NB   8
#define LIN  32768
#define NC1  51
#define NK1  79
#define NSC  9
#define LP1  8192
#define SMAX 64

// scratch (allocation-free rule: device globals)
__device__ float g_bufA[30081024];   // max 8*51*9*8192
__device__ float g_bufB[7520256];    // max 8*51*9*2048
__device__ float g_psum[408 * SMAX];
__device__ float g_psqs[408 * SMAX];
__device__ float g_scale[408];
__device__ float g_shift[408];

// ---------------------------------------------------------------------------
// packed fp32x2 helpers (FFMA2 — only reachable via PTX)
// ---------------------------------------------------------------------------
__device__ __forceinline__ unsigned long long pack2(float lo, float hi) {
    unsigned long long r;
    asm("mov.b64 %0, {%1, %2};" : "=l"(r) : "f"(lo), "f"(hi));
    return r;
}
__device__ __forceinline__ void fma2(unsigned long long& d,
                                     unsigned long long a, unsigned long long b) {
    asm("fma.rn.f32x2 %0, %1, %2, %0;" : "+l"(d) : "l"(a), "l"(b));
}
__device__ __forceinline__ float2 unpack2(unsigned long long v) {
    float2 f;
    asm("mov.b64 {%0, %1}, %2;" : "=f"(f.x), "=f"(f.y) : "l"(v));
    return f;
}

// ---------------------------------------------------------------------------
// Lift (K=79, dilation 2^s, /2^s) fused with pool4. 4co x 4l thread tile,
// inner loop on packed fp32x2 (2 MAC/instr).
// ---------------------------------------------------------------------------
__launch_bounds__(416)
__global__ void lift_pool_kernel(const float* __restrict__ x,
                                 const float* __restrict__ w,
                                 float* __restrict__ out, int s)
{
    extern __shared__ float sm[];
    float* sw = sm;             // [79][52] pre-scaled weights
    float* sx = sm + 79 * 52;   // input window
    const int d = 1 << s;
    const float invd = 1.0f / (float)d;
    const int b   = blockIdx.y;
    const int l0  = blockIdx.x * 128;
    const int tid = threadIdx.x;

    for (int t = tid; t < 79 * 52; t += 416) {
        int k = t / 52, co = t - k * 52;
        sw[t] = (co < NC1) ? w[co * NK1 + k] * invd : 0.0f;
    }
    const int nx = 128 + 78 * d + 8;
    const int gb = l0 - 39 * d;
    const float* xb = x + (size_t)b * LIN;
    for (int t = tid; t < nx; t += 416) {
        int g = gb + t;
        sx[t] = (g >= 0 && g < LIN) ? xb[g] : 0.0f;
    }
    __syncthreads();

    const int lg   = tid & 31;
    const int cg   = tid >> 5;
    const int co0  = cg * 4;
    const int base = lg * 4;
    unsigned long long acc2[4][2] = {};

    if (d >= 4) {
        #pragma unroll 4
        for (int k = 0; k < NK1; ++k) {
            ulonglong2 xq = *reinterpret_cast<const ulonglong2*>(&sx[base + k * d]);
            float4 wv = *reinterpret_cast<const float4*>(&sw[k * 52 + co0]);
            float wa[4] = {wv.x, wv.y, wv.z, wv.w};
            #pragma unroll
            for (int r = 0; r < 4; ++r) {
                unsigned long long wp = pack2(wa[r], wa[r]);
                fma2(acc2[r][0], wp, xq.x);
                fma2(acc2[r][1], wp, xq.y);
            }
        }
    } else if (d == 2) {
        float x0 = sx[base], x1 = sx[base+1], x2 = sx[base+2], x3 = sx[base+3];
        for (int k = 0; k < NK1; ++k) {
            float4 wv = *reinterpret_cast<const float4*>(&sw[k * 52 + co0]);
            float wa[4] = {wv.x, wv.y, wv.z, wv.w};
            unsigned long long xp0 = pack2(x0, x1), xp1 = pack2(x2, x3);
            #pragma unroll
            for (int r = 0; r < 4; ++r) {
                unsigned long long wp = pack2(wa[r], wa[r]);
                fma2(acc2[r][0], wp, xp0);
                fma2(acc2[r][1], wp, xp1);
            }
            x0 = x2; x1 = x3;
            x2 = sx[base + 2*k + 4];
            x3 = sx[base + 2*k + 5];
        }
    } else {
        float x0 = sx[base], x1 = sx[base+1], x2 = sx[base+2], x3 = sx[base+3];
        for (int k = 0; k < NK1; ++k) {
            float4 wv = *reinterpret_cast<const float4*>(&sw[k * 52 + co0]);
            float wa[4] = {wv.x, wv.y, wv.z, wv.w};
            unsigned long long xp0 = pack2(x0, x1), xp1 = pack2(x2, x3);
            #pragma unroll
            for (int r = 0; r < 4; ++r) {
                unsigned long long wp = pack2(wa[r], wa[r]);
                fma2(acc2[r][0], wp, xp0);
                fma2(acc2[r][1], wp, xp1);
            }
            x0 = x1; x1 = x2; x2 = x3;
            x3 = sx[base + k + 4];
        }
    }

    const int lp = blockIdx.x * 32 + lg;
    #pragma unroll
    for (int r = 0; r < 4; ++r) {
        int co = co0 + r;
        if (co < NC1) {
            float2 a = unpack2(acc2[r][0]);
            float2 c = unpack2(acc2[r][1]);
            float m = fmaxf(fmaxf(a.x, a.y), fmaxf(c.x, c.y));
            out[(((size_t)b * NC1 + co) * NSC + s) * LP1 + lp] = m;
        }
    }
}

// ---------------------------------------------------------------------------
// GConvGG, tiled GEMM over ci per (i,k). 4x4 thread tile on fp32x2.
// fuse != 0: apply per-channel BN (g_scale/g_shift) + ReLU when loading Bs.
// ---------------------------------------------------------------------------
template <int COT, int LT>
__launch_bounds__((COT/4)*(LT/4))
__global__ void gg_kernel(const float* __restrict__ in, const float* __restrict__ w,
                          float* __restrict__ out,
                          int Cin, int Cout, int Hin, int Nk, int L, int fuse)
{
    const int CIC = 16;
    const int TLn = LT / 4;
    const int NT  = (COT/4) * TLn;
    __shared__ __align__(16) float As[CIC][COT];
    __shared__ __align__(16) float Bs[CIC][LT];
    __shared__ float ssc[408], ssh[408];

    const int Hout = Hin - Nk + 1;
    const int s   = blockIdx.z % Hout;
    const int b   = blockIdx.z / Hout;
    const int co0 = blockIdx.y * COT;
    const int l0  = blockIdx.x * LT;
    const int tid = threadIdx.x;
    const int tco = (tid / TLn) * 4;
    const int tl  = (tid % TLn) * 4;

    if (fuse) {
        for (int t = tid; t < Cin; t += NT) {
            ssc[t] = g_scale[t];
            ssh[t] = g_shift[t];
        }
    }

    unsigned long long acc2[4][2] = {};

    for (int i = 0; i < Nk; ++i) {
        const int dd = 1 << (s + i);
        const float invd = 1.0f / (float)dd;
        const float* inb = in + (((size_t)b * Cin) * Hin + (s + i)) * L;
        for (int k = 0; k < 3; ++k) {
            const int off = (k - 1) * dd;
            for (int cc = 0; cc < Cin; cc += CIC) {
                __syncthreads();
                for (int t = tid; t < CIC * COT; t += NT) {
                    int ci = cc + t / COT, co = co0 + (t % COT);
                    float v = 0.0f;
                    if (ci < Cin && co < Cout)
                        v = w[(((size_t)co * Cin + ci) * Nk + i) * 3 + k] * invd;
                    As[t / COT][t % COT] = v;
                }
                for (int t = tid; t < CIC * LT; t += NT) {
                    int ci = cc + t / LT;
                    int l  = l0 + off + (t % LT);
                    float v = 0.0f;
                    if (ci < Cin && l >= 0 && l < L) {
                        v = inb[(size_t)ci * Hin * L + l];
                        if (fuse) v = fmaxf(fmaf(v, ssc[ci], ssh[ci]), 0.0f);
                    }
                    Bs[t / LT][t % LT] = v;
                }
                __syncthreads();
                #pragma unroll
                for (int ci = 0; ci < CIC; ++ci) {
                    float4 av = *reinterpret_cast<const float4*>(&As[ci][tco]);
                    ulonglong2 bq = *reinterpret_cast<const ulonglong2*>(&Bs[ci][tl]);
                    float a4[4] = {av.x, av.y, av.z, av.w};
                    #pragma unroll
                    for (int r = 0; r < 4; ++r) {
                        unsigned long long ap = pack2(a4[r], a4[r]);
                        fma2(acc2[r][0], ap, bq.x);
                        fma2(acc2[r][1], ap, bq.y);
                    }
                }
            }
        }
    }

    #pragma unroll
    for (int r = 0; r < 4; ++r) {
        int co = co0 + tco + r;
        if (co < Cout) {
            size_t ob = (((size_t)b * Cout + co) * Hout + s) * L + l0 + tl;
            float2 lo = unpack2(acc2[r][0]);
            float2 hi = unpack2(acc2[r][1]);
            float4 v = make_float4(lo.x, lo.y, hi.x, hi.y);
            *reinterpret_cast<float4*>(&out[ob]) = v;
        }
    }
}

// ---------------------------------------------------------------------------
// BN stats: per-channel per-split partial sums (no atomics, no zeroing).
// grid = (C, S), block = 256
// ---------------------------------------------------------------------------
__global__ void stats_kernel(const float* __restrict__ in, int C, int HL)
{
    const int c  = blockIdx.x;
    const int sp = blockIdx.y, S = gridDim.y;
    float s = 0.0f, s2 = 0.0f;
    for (int b = 0; b < NB; ++b) {
        const float* p = in + ((size_t)b * C + c) * HL;
        for (int r = sp * blockDim.x + threadIdx.x; r < HL; r += S * blockDim.x) {
            float v = p[r];
            s += v; s2 = fmaf(v, v, s2);
        }
    }
    __shared__ float rs[256], rq[256];
    rs[threadIdx.x] = s; rq[threadIdx.x] = s2;
    __syncthreads();
    for (int st = 128; st > 0; st >>= 1) {
        if (threadIdx.x < st) {
            rs[threadIdx.x] += rs[threadIdx.x + st];
            rq[threadIdx.x] += rq[threadIdx.x + st];
        }
        __syncthreads();
    }
    if (threadIdx.x == 0) {
        g_psum[c * SMAX + sp] = rs[0];
        g_psqs[c * SMAX + sp] = rq[0];
    }
}

// reduce partials -> per-channel scale/shift
__global__ void finalize_kernel(const float* __restrict__ gamma,
                                const float* __restrict__ beta,
                                int C, int S, double invN)
{
    int c = blockIdx.x * blockDim.x + threadIdx.x;
    if (c >= C) return;
    double s = 0.0, q = 0.0;
    for (int i = 0; i < S; ++i) {
        s += (double)g_psum[c * SMAX + i];
        q += (double)g_psqs[c * SMAX + i];
    }
    double m   = s * invN;
    double var = q * invN - m * m;
    float inv = rsqrtf((float)var + 2e-5f);
    float sc  = gamma[c] * inv;
    g_scale[c] = sc;
    g_shift[c] = beta[c] - (float)m * sc;
}

// ---------------------------------------------------------------------------
// BN apply + ReLU + pool4 (pooled stages only; scale/shift precomputed)
// ---------------------------------------------------------------------------
__global__ void bn_pool_kernel(const float* __restrict__ in, float* __restrict__ out,
                               int C, int H, int Lin)
{
    __shared__ float ssc[408], ssh[408];
    for (int c = threadIdx.x; c < C; c += blockDim.x) {
        ssc[c] = g_scale[c];
        ssh[c] = g_shift[c];
    }
    __syncthreads();

    const int Lout = Lin / 4;
    const size_t n = (size_t)NB * C * H * Lout;
    for (size_t i = (size_t)blockIdx.x * blockDim.x + threadIdx.x; i < n;
         i += (size_t)gridDim.x * blockDim.x) {
        int lp = (int)(i % Lout);
        size_t t = i / Lout;
        int h = (int)(t % H); t /= H;           // t = b*C + c
        int c = (int)(t % C);
        size_t ibase = (t * (size_t)H + h) * (size_t)Lin;
        float sc = ssc[c], sh = ssh[c];
        const float* p = in + ibase + 4 * (size_t)lp;
        float y0 = fmaf(p[0], sc, sh);
        float y1 = fmaf(p[1], sc, sh);
        float y2 = fmaf(p[2], sc, sh);
        float y3 = fmaf(p[3], sc, sh);
        float y = fmaxf(fmaxf(y0, y1), fmaxf(y2, y3));
        out[i] = fmaxf(y, 0.0f);
    }
}

// ---------------------------------------------------------------------------
// Final: fused bn10+relu, mean over L=32, 1x1 classifier -> out [8,10]
// ---------------------------------------------------------------------------
__global__ void final_kernel(const float* __restrict__ in,   // raw [8][408][32]
                             const float* __restrict__ w11,
                             float* __restrict__ out)
{
    __shared__ float mean[NB * 408];
    for (int i = threadIdx.x; i < NB * 408; i += blockDim.x) {
        int c = i % 408;
        float sc = g_scale[c], sh = g_shift[c];
        const float* p = in + (size_t)i * 32;
        float s = 0.0f;
        #pragma unroll
        for (int j = 0; j < 32; ++j)
            s += fmaxf(fmaf(p[j], sc, sh), 0.0f);
        mean[i] = s * (1.0f / 32.0f);
    }
    __syncthreads();
    for (int i = threadIdx.x; i < NB * 10; i += blockDim.x) {
        int b = i / 10, cls = i - b * 10;
        const float* mb = &mean[b * 408];
        const float* wr = &w11[cls * 408];
        float s = 0.0f;
        for (int ci = 0; ci < 408; ++ci) s = fmaf(mb[ci], wr[ci], s);
        out[i] = s;
    }
}

// ---------------------------------------------------------------------------
// Host side
// ---------------------------------------------------------------------------
static void bn_stats(const float* in, const float* g, const float* bta, int C, int H, int Lin)
{
    int HL = H * Lin;
    int S = (NB * HL) / (256 * 16);
    if (S < 1) S = 1; if (S > SMAX) S = SMAX;
    stats_kernel<<<dim3(C, S), 256>>>(in, C, HL);
    double invN = 1.0 / ((double)NB * HL);
    finalize_kernel<<<(C + 255) / 256, 256>>>(g, bta, C, S, invN);
}

static void bn_pool(const float* in, float* out, int C, int H, int Lin)
{
    size_t n = (size_t)NB * C * H * (Lin / 4);
    int grid = (int)((n + 255) / 256);
    if (grid > 8192) grid = 8192;
    bn_pool_kernel<<<grid, 256>>>(in, out, C, H, Lin);
}

static void gg(const float* in, const float* w, float* out,
               int Cin, int Cout, int Hin, int Nk, int L, int fuse)
{
    int Hout = Hin - Nk + 1;
    if (L >= 64)
        gg_kernel<64, 64><<<dim3(L / 64, (Cout + 63) / 64, NB * Hout), 256>>>(
            in, w, out, Cin, Cout, Hin, Nk, L, fuse);
    else
        gg_kernel<64, 32><<<dim3(L / 32, (Cout + 63) / 64, NB * Hout), 128>>>(
            in, w, out, Cin, Cout, Hin, Nk, L, fuse);
}

extern "C" void kernel_launch(void* const* d_in, const int* in_sizes, int n_in,
                              void* d_out, int out_size)
{
    const float* x   = (const float*)d_in[0];
    const float* w1  = (const float*)d_in[1];
    const float* w2  = (const float*)d_in[2];
    const float* w3  = (const float*)d_in[3];
    const float* w4  = (const float*)d_in[4];
    const float* w5  = (const float*)d_in[5];
    const float* w6  = (const float*)d_in[6];
    const float* w7  = (const float*)d_in[7];
    const float* w8  = (const float*)d_in[8];
    const float* w9  = (const float*)d_in[9];
    const float* w10 = (const float*)d_in[10];
    const float* w11 = (const float*)d_in[11];
    const float* gb[20];
    for (int i = 0; i < 20; ++i) gb[i] = (const float*)d_in[12 + i];

    float *A, *B;
    cudaGetSymbolAddress((void**)&A, g_bufA);
    cudaGetSymbolAddress((void**)&B, g_bufB);

    cudaFuncSetAttribute(lift_pool_kernel,
                         cudaFuncAttributeMaxDynamicSharedMemorySize, 98304);

    // lift + pool4 -> A [8,51,9,8192]
    for (int s = 0; s < NSC; ++s) {
        int d = 1 << s;
        size_t smem = (size_t)(79 * 52 + 128 + 78 * d + 8) * sizeof(float);
        lift_pool_kernel<<<dim3(LIN / 128, NB), 416, smem>>>(x, w1, A, s);
    }

    bn_stats(A, gb[0], gb[1], 51, 9, 8192);
    bn_pool(A, B, 51, 9, 8192);                  // -> B [8,51,9,2048]
    gg(B, w2, A, 51, 51, 9, 3, 2048, 0);         // -> A [8,51,7,2048]
    bn_stats(A, gb[2], gb[3], 51, 7, 2048);
    gg(A, w3, B, 51, 51, 7, 1, 2048, 1);         // -> B [8,51,7,2048]
    bn_stats(B, gb[4], gb[5], 51, 7, 2048);
    bn_pool(B, A, 51, 7, 2048);                  // -> A [8,51,7,512]
    gg(A, w4, B, 51, 102, 7, 3, 512, 0);         // -> B [8,102,5,512]
    bn_stats(B, gb[6], gb[7], 102, 5, 512);
    gg(B, w5, A, 102, 102, 5, 1, 512, 1);        // -> A [8,102,5,512]
    bn_stats(A, gb[8], gb[9], 102, 5, 512);
    bn_pool(A, B, 102, 5, 512);                  // -> B [8,102,5,128]
    gg(B, w6, A, 102, 204, 5, 3, 128, 0);        // -> A [8,204,3,128]
    bn_stats(A, gb[10], gb[11], 204, 3, 128);
    gg(A, w7, B, 204, 204, 3, 1, 128, 1);        // -> B [8,204,3,128]
    bn_stats(B, gb[12], gb[13], 204, 3, 128);
    gg(B, w8, A, 204, 204, 3, 1, 128, 1);        // -> A [8,204,3,128]
    bn_stats(A, gb[14], gb[15], 204, 3, 128);
    bn_pool(A, B, 204, 3, 128);                  // -> B [8,204,3,32]
    gg(B, w9, A, 204, 408, 3, 3, 32, 0);         // -> A [8,408,1,32]
    bn_stats(A, gb[16], gb[17], 408, 1, 32);
    gg(A, w10, B, 408, 408, 1, 1, 32, 1);        // -> B [8,408,1,32]
    bn_stats(B, gb[18], gb[19], 408, 1, 32);

    final_kernel<<<1, 512>>>(B, w11, (float*)d_out);
}